// round 7
// baseline (speedup 1.0000x reference)
#include <cuda_runtime.h>
#include <math.h>

#define BN 32
#define TN 4096
#define UN 256
#define NJ 1024
#define CL 8

// ---------------- static device scratch (no runtime allocation) -------------
__device__ float g_Zx[(size_t)TN * BN * NJ];   // [t*32+b][j] input projection
__device__ float g_Wp[512 * NJ];               // packed W: rows 0..255 s-part, 256..511 x-part; col j=g*256+u

// ---------------- helpers ----------------------------------------------------
__device__ __forceinline__ unsigned smem_u32(const void* p) {
    unsigned a;
    asm("{ .reg .u64 t; cvta.to.shared.u64 t, %1; cvt.u32.u64 %0, t; }"
        : "=r"(a) : "l"(p));
    return a;
}
__device__ __forceinline__ unsigned long long pk2(float v) {
    unsigned long long r; unsigned u = __float_as_uint(v);
    asm("mov.b64 %0, {%1, %1};" : "=l"(r) : "r"(u));
    return r;
}
__device__ __forceinline__ unsigned long long pack2(float lo, float hi) {
    unsigned long long r;
    asm("mov.b64 %0, {%1, %2};" : "=l"(r)
        : "r"(__float_as_uint(lo)), "r"(__float_as_uint(hi)));
    return r;
}
__device__ __forceinline__ unsigned long long fma2(unsigned long long a,
                                                   unsigned long long b,
                                                   unsigned long long c) {
    unsigned long long d;
    asm("fma.rn.f32x2 %0, %1, %2, %3;" : "=l"(d) : "l"(a), "l"(b), "l"(c));
    return d;
}
__device__ __forceinline__ float2 upk2(unsigned long long v) {
    unsigned lo, hi;
    asm("mov.b64 {%0, %1}, %2;" : "=r"(lo), "=r"(hi) : "l"(v));
    return make_float2(__uint_as_float(lo), __uint_as_float(hi));
}
__device__ __forceinline__ unsigned mapa_u32(unsigned local, unsigned rank) {
    unsigned r;
    asm("mapa.shared::cluster.u32 %0, %1, %2;" : "=r"(r) : "r"(local), "r"(rank));
    return r;
}
__device__ __forceinline__ void mbar_init(unsigned addr, unsigned cnt) {
    asm volatile("mbarrier.init.shared.b64 [%0], %1;" :: "r"(addr), "r"(cnt) : "memory");
}
__device__ __forceinline__ void mbar_arrive_rel_cluster(unsigned addr) {
    asm volatile("mbarrier.arrive.release.cluster.shared::cluster.b64 _, [%0];"
                 :: "r"(addr) : "memory");
}
__device__ __forceinline__ void mbar_wait_cluster(unsigned addr, unsigned parity) {
    asm volatile(
        "{\n\t"
        ".reg .pred P;\n\t"
        "WL_%=:\n\t"
        "mbarrier.try_wait.parity.acquire.cluster.shared::cta.b64 P, [%0], %1;\n\t"
        "@!P bra WL_%=;\n\t"
        "}"
        :: "r"(addr), "r"(parity) : "memory");
}
__device__ __forceinline__ void st_cluster_v4(unsigned addr, float4 v) {
    asm volatile("st.shared::cluster.v4.f32 [%0], {%1, %2, %3, %4};"
                 :: "r"(addr), "f"(v.x), "f"(v.y), "f"(v.z), "f"(v.w) : "memory");
}
// unified gate nonlinearity: A + B / (1 + exp(a))
//   sigmoid(z): a=-z, A=0, B=1      tanh(z): a=2z, A=1, B=-2
__device__ __forceinline__ float gatefn(float a, float A, float B) {
    float e = __expf(a);
    float r = __fdividef(B, 1.0f + e);
    return A + r;
}
__device__ __forceinline__ float tanh_fast(float z) {
    float e = __expf(2.0f * z);
    return 1.0f - __fdividef(2.0f, 1.0f + e);
}

// ---------------- alignment rotator (so ncu -s 5 lands on k_rec) ------------
__global__ void k_nop() {}

// ---------------- kernel 0: pack weights ------------------------------------
__global__ __launch_bounds__(256) void k_init(const float* __restrict__ Wf,
                                              const float* __restrict__ Wi,
                                              const float* __restrict__ Wc,
                                              const float* __restrict__ Wo) {
    int idx = blockIdx.x * blockDim.x + threadIdx.x;
    if (idx < 512 * 1024) {
        int k = idx >> 10, j = idx & 1023;
        int g = j >> 8,    u = j & 255;
        const float* W = (g == 0) ? Wf : (g == 1) ? Wi : (g == 2) ? Wc : Wo;
        g_Wp[idx] = W[k * 256 + u];
    }
}

// ---------------- kernel 1: input projection GEMM ---------------------------
__global__ __launch_bounds__(256) void k_gemm(const float* __restrict__ x) {
    __shared__ __align__(16) float As[16][64];
    __shared__ __align__(16) float Bs[16][64];

    const int tid = threadIdx.x;
    const int n0  = blockIdx.x * 64;
    const int m0  = blockIdx.y * 64;
    const int tm  = tid >> 4, tn = tid & 15;
    const int ar  = tid >> 2, akq = tid & 3;
    const int bkr = tid >> 4, bnq = tid & 15;

    const int m_glob = m0 + ar;
    const int bb = m_glob & 31, tt = m_glob >> 5;
    const float* arow = x + ((size_t)bb * TN + tt) * 256;

    unsigned long long a00=0, a01=0, a10=0, a11=0, a20=0, a21=0, a30=0, a31=0;

    float4 av = *(const float4*)(arow + akq * 4);
    float4 bv = *(const float4*)(g_Wp + (size_t)(256 + bkr) * NJ + n0 + bnq * 4);

    for (int k0 = 0; k0 < 256; k0 += 16) {
        __syncthreads();
        As[akq * 4 + 0][ar] = av.x;
        As[akq * 4 + 1][ar] = av.y;
        As[akq * 4 + 2][ar] = av.z;
        As[akq * 4 + 3][ar] = av.w;
        *(float4*)&Bs[bkr][bnq * 4] = bv;
        __syncthreads();

        if (k0 + 16 < 256) {
            av = *(const float4*)(arow + k0 + 16 + akq * 4);
            bv = *(const float4*)(g_Wp + (size_t)(256 + k0 + 16 + bkr) * NJ + n0 + bnq * 4);
        }
        #pragma unroll
        for (int kk = 0; kk < 16; kk++) {
            float4 a = *(const float4*)&As[kk][tm * 4];
            ulonglong2 w = *(const ulonglong2*)&Bs[kk][tn * 4];
            unsigned long long p;
            p = pk2(a.x); a00 = fma2(p, w.x, a00); a01 = fma2(p, w.y, a01);
            p = pk2(a.y); a10 = fma2(p, w.x, a10); a11 = fma2(p, w.y, a11);
            p = pk2(a.z); a20 = fma2(p, w.x, a20); a21 = fma2(p, w.y, a21);
            p = pk2(a.w); a30 = fma2(p, w.x, a30); a31 = fma2(p, w.y, a31);
        }
    }
    float2 lo, hi;
    lo = upk2(a00); hi = upk2(a01);
    *(float4*)(g_Zx + (size_t)(m0 + tm*4 + 0) * NJ + n0 + tn*4) = make_float4(lo.x, lo.y, hi.x, hi.y);
    lo = upk2(a10); hi = upk2(a11);
    *(float4*)(g_Zx + (size_t)(m0 + tm*4 + 1) * NJ + n0 + tn*4) = make_float4(lo.x, lo.y, hi.x, hi.y);
    lo = upk2(a20); hi = upk2(a21);
    *(float4*)(g_Zx + (size_t)(m0 + tm*4 + 2) * NJ + n0 + tn*4) = make_float4(lo.x, lo.y, hi.x, hi.y);
    lo = upk2(a30); hi = upk2(a31);
    *(float4*)(g_Zx + (size_t)(m0 + tm*4 + 3) * NJ + n0 + tn*4) = make_float4(lo.x, lo.y, hi.x, hi.y);
}

// ---------------- kernel 2: persistent recurrence (clusters + DSMEM) --------
// 16 clusters x 8 CTAs. Cluster c owns batches {2c, 2c+1}. CTA rank r owns
// u-range [r*32, r*32+32). Per-SOURCE mbarriers: warp w consumes state slice
// k in [32w, 32w+32) which is produced exactly by cluster rank w, so warp w
// waits only mbar[w] -> arrival skew overlaps with other warps' FMAs.
__global__ __launch_bounds__(256, 1) __cluster_dims__(CL, 1, 1)
void k_rec(float* __restrict__ out, const float* __restrict__ h0) {
    __shared__ __align__(16) float Ssm[2][512];       // [parity][k*2 + b]
    __shared__ __align__(16) float Zsm[16][272];      // [kg][b*128 + jj], padded rows
    __shared__ __align__(16) float stg[64];           // [uu*2 + b]
    __shared__ __align__(8)  unsigned long long mbars[8];  // one per source rank

    const int tid = threadIdx.x;
    unsigned r;
    asm("mov.u32 %0, %%cluster_ctarank;" : "=r"(r));
    const int team = blockIdx.x >> 3;
    const int b0   = team * 2;
    const int u0   = (int)r * 32;

    const int wid = tid >> 5;                 // warp = source rank it consumes
    const int kg  = tid >> 4, jq = tid & 15, kbeg = kg * 16;
    const int jj  = tid & 127, bb = tid >> 7; // reduce/gate role (zi == tid)
    const int gg  = jj & 3,    uu = jj >> 2;
    const int jcol = gg * 256 + u0 + uu;
    const size_t c_off = (size_t)BN * TN * UN;

    if (tid < 8) mbar_init(smem_u32(&mbars[tid]), 1);

    // initial state for step 0
    Ssm[0][tid * 2 + 0] = h0[(b0 + 0) * 256 + tid];
    Ssm[0][tid * 2 + 1] = h0[(b0 + 1) * 256 + tid];

    // gate-fn constants for this thread's gate (f,i,g: sigmoid; o: tanh)
    const float gA = (gg == 3) ? 1.0f : 0.0f;
    const float gB = (gg == 3) ? -2.0f : 1.0f;
    const float gS = (gg == 3) ? 2.0f : -1.0f;   // argument scale: exp(gS*z)

    // weight tile -> registers: 16 k x 4 u64; u64 m pairs cols (jq+32m, jq+32m+16)
    unsigned long long w[16][4];
    #pragma unroll
    for (int k = 0; k < 16; k++) {
        const float* row = g_Wp + (size_t)(kbeg + k) * NJ;
        #pragma unroll
        for (int m = 0; m < 4; m++) {
            int jA = jq + 32 * m, jB = jA + 16;
            int cA = (jA & 3) * 256 + u0 + (jA >> 2);
            int cB = (jB & 3) * 256 + u0 + (jB >> 2);
            w[k][m] = pack2(__ldg(row + cA), __ldg(row + cB));
        }
    }

    // pusher precompute (tid < 8: pushes this CTA's slice to rank dst=tid)
    unsigned dstA = 0, rbar = 0;
    if (tid < 8) {
        dstA = mapa_u32(smem_u32(&Ssm[0][u0 * 2]), (unsigned)tid);
        rbar = mapa_u32(smem_u32(&mbars[r]), (unsigned)tid);
    }

    __syncthreads();
    asm volatile("barrier.cluster.arrive.aligned;" ::: "memory");
    asm volatile("barrier.cluster.wait.aligned;" ::: "memory");

    const unsigned mybar = smem_u32(&mbars[wid]);

    for (int t = 0; t < TN; t++) {
        const int cur = t & 1;

        // prefetch input projection (independent of state)
        float zx = __ldcg(&g_Zx[((size_t)(t * 32 + b0 + bb)) * NJ + jcol]);

        // warp-sliced wait: only this warp's source slice must have arrived
        if (t > 0) mbar_wait_cluster(mybar, (unsigned)((t - 1) & 1));

        // recurrent matmul: 16 k x 4 u64 x 2 batches, weights in registers
        unsigned long long acc[2][4] = {{0,0,0,0},{0,0,0,0}};
        #pragma unroll
        for (int k = 0; k < 16; k++) {
            float2 s = *(const float2*)&Ssm[cur][(kbeg + k) * 2];
            unsigned long long p0 = pk2(s.x), p1 = pk2(s.y);
            #pragma unroll
            for (int m = 0; m < 4; m++) {
                acc[0][m] = fma2(p0, w[k][m], acc[0][m]);
                acc[1][m] = fma2(p1, w[k][m], acc[1][m]);
            }
        }
        // conflict-free partial stores: lane-consecutive STS.32
        #pragma unroll
        for (int b = 0; b < 2; b++) {
            #pragma unroll
            for (int m = 0; m < 4; m++) {
                float2 v = upk2(acc[b][m]);
                Zsm[kg][b * 128 + jq + 32 * m]      = v.x;
                Zsm[kg][b * 128 + jq + 32 * m + 16] = v.y;
            }
        }

        __syncthreads();

        // reduce 16 k-partials + input projection
        float z = zx;
        #pragma unroll
        for (int g = 0; g < 16; g++) z += Zsm[g][bb * 128 + jj];

        // per-lane nonlinearity (branch-free), then gather 4 gates via shuffle
        float v = gatefn(gS * z, gA, gB);
        const int base = (tid & 31) & ~3;
        float fv = __shfl_sync(0xFFFFFFFFu, v, base + 0);
        float iv = __shfl_sync(0xFFFFFFFFu, v, base + 1);
        float gv = __shfl_sync(0xFFFFFFFFu, v, base + 2);
        float ov = __shfl_sync(0xFFFFFFFFu, v, base + 3);

        if ((tid & 3) == 0) {
            float s_old = Ssm[cur][(u0 + uu) * 2 + bb];
            float c  = iv * gv + fv * s_old;
            float ct = tanh_fast(c);
            float h  = ov * ct;
            stg[uu * 2 + bb] = ct;
            size_t oidx = ((size_t)(b0 + bb) * TN + t) * UN + (u0 + uu);
            out[oidx]         = h;
            out[c_off + oidx] = ct;
        }
        __syncthreads();

        // push new state slice to all 8 cluster CTAs' Ssm[(t+1)&1], then arrive
        if (t + 1 < TN && tid < 8) {
            unsigned dst = dstA + (unsigned)(((t + 1) & 1) * 2048);
            #pragma unroll
            for (int i2 = 0; i2 < 16; i2++) {
                float4 vv = *(const float4*)&stg[i2 * 4];
                st_cluster_v4(dst + i2 * 16, vv);
            }
            mbar_arrive_rel_cluster(rbar);
        }
    }
}

// ---------------- launcher ---------------------------------------------------
extern "C" void kernel_launch(void* const* d_in, const int* in_sizes, int n_in,
                              void* d_out, int out_size) {
    const float* x  = (const float*)d_in[0];
    const float* h0 = (const float*)d_in[1];
    const float* Wf = (const float*)d_in[2];
    const float* Wi = (const float*)d_in[3];
    const float* Wc = (const float*)d_in[4];
    const float* Wo = (const float*)d_in[5];
    float* out = (float*)d_out;

    k_nop<<<1, 1>>>();
    k_init<<<2048, 256>>>(Wf, Wi, Wc, Wo);
    dim3 gg(NJ / 64, (TN * BN) / 64);   // (16, 2048)
    k_gemm<<<gg, 256>>>(x);
    k_rec<<<128, 256>>>(out, h0);
}

// round 8
// speedup vs baseline: 1.1106x; 1.1106x over previous
#include <cuda_runtime.h>
#include <math.h>

#define BN 32
#define TN 4096
#define UN 256
#define NJ 1024
#define CL 8

// ---------------- static device scratch (no runtime allocation) -------------
__device__ float g_Zx[(size_t)TN * BN * NJ];   // [t*32+b][j] input projection
__device__ float g_Wp[512 * NJ];               // packed W: rows 0..255 s-part, 256..511 x-part; col j=g*256+u

// ---------------- helpers ----------------------------------------------------
__device__ __forceinline__ unsigned smem_u32(const void* p) {
    unsigned a;
    asm("{ .reg .u64 t; cvta.to.shared.u64 t, %1; cvt.u32.u64 %0, t; }"
        : "=r"(a) : "l"(p));
    return a;
}
__device__ __forceinline__ unsigned long long pk2(float v) {
    unsigned long long r; unsigned u = __float_as_uint(v);
    asm("mov.b64 %0, {%1, %1};" : "=l"(r) : "r"(u));
    return r;
}
__device__ __forceinline__ unsigned long long pack2(float lo, float hi) {
    unsigned long long r;
    asm("mov.b64 %0, {%1, %2};" : "=l"(r)
        : "r"(__float_as_uint(lo)), "r"(__float_as_uint(hi)));
    return r;
}
__device__ __forceinline__ unsigned long long fma2(unsigned long long a,
                                                   unsigned long long b,
                                                   unsigned long long c) {
    unsigned long long d;
    asm("fma.rn.f32x2 %0, %1, %2, %3;" : "=l"(d) : "l"(a), "l"(b), "l"(c));
    return d;
}
__device__ __forceinline__ float2 upk2(unsigned long long v) {
    unsigned lo, hi;
    asm("mov.b64 {%0, %1}, %2;" : "=r"(lo), "=r"(hi) : "l"(v));
    return make_float2(__uint_as_float(lo), __uint_as_float(hi));
}
__device__ __forceinline__ unsigned mapa_u32(unsigned local, unsigned rank) {
    unsigned r;
    asm("mapa.shared::cluster.u32 %0, %1, %2;" : "=r"(r) : "r"(local), "r"(rank));
    return r;
}
__device__ __forceinline__ void mbar_init(unsigned addr, unsigned cnt) {
    asm volatile("mbarrier.init.shared.b64 [%0], %1;" :: "r"(addr), "r"(cnt) : "memory");
}
__device__ __forceinline__ void mbar_arrive_rel_cluster(unsigned addr) {
    asm volatile("mbarrier.arrive.release.cluster.shared::cluster.b64 _, [%0];"
                 :: "r"(addr) : "memory");
}
__device__ __forceinline__ void mbar_wait_cluster(unsigned addr, unsigned parity) {
    asm volatile(
        "{\n\t"
        ".reg .pred P;\n\t"
        "WL_%=:\n\t"
        "mbarrier.try_wait.parity.acquire.cluster.shared::cta.b64 P, [%0], %1, 0x989680;\n\t"
        "@!P bra WL_%=;\n\t"
        "}"
        :: "r"(addr), "r"(parity) : "memory");
}
__device__ __forceinline__ void st_cluster_v4(unsigned addr, float4 v) {
    asm volatile("st.shared::cluster.v4.f32 [%0], {%1, %2, %3, %4};"
                 :: "r"(addr), "f"(v.x), "f"(v.y), "f"(v.z), "f"(v.w) : "memory");
}
// unified gate nonlinearity: A + B / (1 + exp(s*z))
__device__ __forceinline__ float gatefn(float a, float A, float B) {
    float e = __expf(a);
    float r = __fdividef(B, 1.0f + e);
    return A + r;
}
__device__ __forceinline__ float tanh_fast(float z) {
    float e = __expf(2.0f * z);
    return 1.0f - __fdividef(2.0f, 1.0f + e);
}

// ---------------- alignment rotator (so ncu -s 5 lands on k_rec) ------------
__global__ void k_nop() {}

// ---------------- kernel 0: pack weights ------------------------------------
__global__ __launch_bounds__(256) void k_init(const float* __restrict__ Wf,
                                              const float* __restrict__ Wi,
                                              const float* __restrict__ Wc,
                                              const float* __restrict__ Wo) {
    int idx = blockIdx.x * blockDim.x + threadIdx.x;
    if (idx < 512 * 1024) {
        int k = idx >> 10, j = idx & 1023;
        int g = j >> 8,    u = j & 255;
        const float* W = (g == 0) ? Wf : (g == 1) ? Wi : (g == 2) ? Wc : Wo;
        g_Wp[idx] = W[k * 256 + u];
    }
}

// ---------------- kernel 1: input projection GEMM ---------------------------
__global__ __launch_bounds__(256) void k_gemm(const float* __restrict__ x) {
    __shared__ __align__(16) float As[16][64];
    __shared__ __align__(16) float Bs[16][64];

    const int tid = threadIdx.x;
    const int n0  = blockIdx.x * 64;
    const int m0  = blockIdx.y * 64;
    const int tm  = tid >> 4, tn = tid & 15;
    const int ar  = tid >> 2, akq = tid & 3;
    const int bkr = tid >> 4, bnq = tid & 15;

    const int m_glob = m0 + ar;
    const int bb = m_glob & 31, tt = m_glob >> 5;
    const float* arow = x + ((size_t)bb * TN + tt) * 256;

    unsigned long long a00=0, a01=0, a10=0, a11=0, a20=0, a21=0, a30=0, a31=0;

    float4 av = *(const float4*)(arow + akq * 4);
    float4 bv = *(const float4*)(g_Wp + (size_t)(256 + bkr) * NJ + n0 + bnq * 4);

    for (int k0 = 0; k0 < 256; k0 += 16) {
        __syncthreads();
        As[akq * 4 + 0][ar] = av.x;
        As[akq * 4 + 1][ar] = av.y;
        As[akq * 4 + 2][ar] = av.z;
        As[akq * 4 + 3][ar] = av.w;
        *(float4*)&Bs[bkr][bnq * 4] = bv;
        __syncthreads();

        if (k0 + 16 < 256) {
            av = *(const float4*)(arow + k0 + 16 + akq * 4);
            bv = *(const float4*)(g_Wp + (size_t)(256 + k0 + 16 + bkr) * NJ + n0 + bnq * 4);
        }
        #pragma unroll
        for (int kk = 0; kk < 16; kk++) {
            float4 a = *(const float4*)&As[kk][tm * 4];
            ulonglong2 w = *(const ulonglong2*)&Bs[kk][tn * 4];
            unsigned long long p;
            p = pk2(a.x); a00 = fma2(p, w.x, a00); a01 = fma2(p, w.y, a01);
            p = pk2(a.y); a10 = fma2(p, w.x, a10); a11 = fma2(p, w.y, a11);
            p = pk2(a.z); a20 = fma2(p, w.x, a20); a21 = fma2(p, w.y, a21);
            p = pk2(a.w); a30 = fma2(p, w.x, a30); a31 = fma2(p, w.y, a31);
        }
    }
    float2 lo, hi;
    lo = upk2(a00); hi = upk2(a01);
    *(float4*)(g_Zx + (size_t)(m0 + tm*4 + 0) * NJ + n0 + tn*4) = make_float4(lo.x, lo.y, hi.x, hi.y);
    lo = upk2(a10); hi = upk2(a11);
    *(float4*)(g_Zx + (size_t)(m0 + tm*4 + 1) * NJ + n0 + tn*4) = make_float4(lo.x, lo.y, hi.x, hi.y);
    lo = upk2(a20); hi = upk2(a21);
    *(float4*)(g_Zx + (size_t)(m0 + tm*4 + 2) * NJ + n0 + tn*4) = make_float4(lo.x, lo.y, hi.x, hi.y);
    lo = upk2(a30); hi = upk2(a31);
    *(float4*)(g_Zx + (size_t)(m0 + tm*4 + 3) * NJ + n0 + tn*4) = make_float4(lo.x, lo.y, hi.x, hi.y);
}

// ---------------- kernel 2: persistent recurrence (clusters + DSMEM) --------
// 16 clusters x 8 CTAs. Cluster c owns batches {2c, 2c+1}. CTA rank r owns
// u-range [r*32, r*32+32), weights in registers.
// Push: warp w sends this CTA's state slice to rank w (16 lanes x 1 float4,
//       single-target), all 16 lanes arrive at remote mbars[src=r] (count=16).
// Wait: warp w consumes k-slice [32w,32w+32) == u-slice of source w, so it
//       waits only mbars[w] -> skew overlaps other warps' FMAs.
__global__ __launch_bounds__(256, 1) __cluster_dims__(CL, 1, 1)
void k_rec(float* __restrict__ out, const float* __restrict__ h0) {
    __shared__ __align__(16) float Ssm[2][512];       // [parity][k*2 + b]
    __shared__ __align__(16) float Zsm[16][272];      // [kg][b*128 + jj], padded
    __shared__ __align__(16) float stg[64];           // [uu*2 + b]
    __shared__ __align__(8)  unsigned long long mbars[2][8];  // [parity][source]

    const int tid  = threadIdx.x;
    const int lane = tid & 31;
    const int wid  = tid >> 5;
    unsigned r;
    asm("mov.u32 %0, %%cluster_ctarank;" : "=r"(r));
    const int team = blockIdx.x >> 3;
    const int b0   = team * 2;
    const int u0   = (int)r * 32;

    const int kg = tid >> 4, jq = tid & 15, kbeg = kg * 16;
    const int jj = tid & 127, bb = tid >> 7;     // reduce/gate role (zi == tid)
    const int gg = jj & 3,    uu = jj >> 2;
    const int jcol = gg * 256 + u0 + uu;
    const size_t c_off = (size_t)BN * TN * UN;

    if (tid < 16) mbar_init(smem_u32(&mbars[tid >> 3][tid & 7]), 16);

    // initial state for step 0
    Ssm[0][tid * 2 + 0] = h0[(b0 + 0) * 256 + tid];
    Ssm[0][tid * 2 + 1] = h0[(b0 + 1) * 256 + tid];

    // gate-fn constants (f,i,g: sigmoid; o: tanh)
    const float gA = (gg == 3) ? 1.0f : 0.0f;
    const float gB = (gg == 3) ? -2.0f : 1.0f;
    const float gS = (gg == 3) ? 2.0f : -1.0f;

    // weight tile -> registers: u64 m pairs cols (jq+32m, jq+32m+16)
    unsigned long long w[16][4];
    #pragma unroll
    for (int k = 0; k < 16; k++) {
        const float* row = g_Wp + (size_t)(kbeg + k) * NJ;
        #pragma unroll
        for (int m = 0; m < 4; m++) {
            int jA = jq + 32 * m, jB = jA + 16;
            int cA = (jA & 3) * 256 + u0 + (jA >> 2);
            int cB = (jB & 3) * 256 + u0 + (jB >> 2);
            w[k][m] = pack2(__ldg(row + cA), __ldg(row + cB));
        }
    }

    // push precompute: my warp's target rank == wid
    unsigned dst0 = 0, dst1 = 0, rbar0 = 0, rbar1 = 0;
    if (lane < 16) {
        unsigned local = smem_u32(&Ssm[0][u0 * 2]) + (unsigned)(lane * 16);
        dst0 = mapa_u32(local, (unsigned)wid);
        dst1 = dst0 + 2048;                       // Ssm[1] is +512 floats
        rbar0 = mapa_u32(smem_u32(&mbars[0][r]), (unsigned)wid);
        rbar1 = mapa_u32(smem_u32(&mbars[1][r]), (unsigned)wid);
    }
    const unsigned mywait0 = smem_u32(&mbars[0][wid]);
    const unsigned mywait1 = smem_u32(&mbars[1][wid]);

    // per-step incremented pointers
    const float* zxp = g_Zx + (size_t)(b0 + bb) * NJ + jcol;     // += 32*NJ
    float* outH = out + (size_t)(b0 + bb) * TN * UN + (u0 + uu); // += UN

    __syncthreads();
    asm volatile("barrier.cluster.arrive.aligned;" ::: "memory");
    asm volatile("barrier.cluster.wait.aligned;" ::: "memory");

    for (int t = 0; t < TN; t++) {
        const int cur = t & 1;

        // prefetch input projection (independent of state)
        float zx = __ldcg(zxp);
        zxp += 32 * NJ;

        // warp-sliced wait: exchange e = t-1, barrier e&1, parity (e>>1)&1
        if (t > 0) {
            const int e = t - 1;
            mbar_wait_cluster((e & 1) ? mywait1 : mywait0, (unsigned)((e >> 1) & 1));
        }

        // recurrent matmul: 16 k x 4 u64 x 2 batches, weights in registers
        unsigned long long acc[2][4] = {{0,0,0,0},{0,0,0,0}};
        const float2* Sp = (const float2*)&Ssm[cur][kbeg * 2];
        #pragma unroll
        for (int k = 0; k < 16; k++) {
            float2 s = Sp[k];
            unsigned long long p0 = pk2(s.x), p1 = pk2(s.y);
            #pragma unroll
            for (int m = 0; m < 4; m++) {
                acc[0][m] = fma2(p0, w[k][m], acc[0][m]);
                acc[1][m] = fma2(p1, w[k][m], acc[1][m]);
            }
        }
        // conflict-free partial stores (lane-consecutive STS.32)
        #pragma unroll
        for (int b = 0; b < 2; b++) {
            #pragma unroll
            for (int m = 0; m < 4; m++) {
                float2 v = upk2(acc[b][m]);
                Zsm[kg][b * 128 + jq + 32 * m]      = v.x;
                Zsm[kg][b * 128 + jq + 32 * m + 16] = v.y;
            }
        }

        __syncthreads();

        // reduce 16 k-partials + input projection
        float z = zx;
        #pragma unroll
        for (int g = 0; g < 16; g++) z += Zsm[g][bb * 128 + jj];

        // branch-free per-lane nonlinearity, gather 4 gates via shuffle
        float v = gatefn(gS * z, gA, gB);
        const int base = lane & ~3;
        float fv = __shfl_sync(0xFFFFFFFFu, v, base + 0);
        float iv = __shfl_sync(0xFFFFFFFFu, v, base + 1);
        float gv = __shfl_sync(0xFFFFFFFFu, v, base + 2);
        float ov = __shfl_sync(0xFFFFFFFFu, v, base + 3);

        if ((tid & 3) == 0) {
            float s_old = Ssm[cur][(u0 + uu) * 2 + bb];
            float c  = iv * gv + fv * s_old;
            float ct = tanh_fast(c);
            float h  = ov * ct;
            stg[uu * 2 + bb] = ct;
            outH[0]     = h;
            outH[c_off] = ct;
        }
        outH += UN;
        __syncthreads();

        // push: warp w -> rank w; 16 coalesced float4 stores + 16 release-arrives
        if (t + 1 < TN && lane < 16) {
            float4 vv = *(const float4*)&stg[lane * 4];
            st_cluster_v4(((t + 1) & 1) ? dst1 : dst0, vv);
            mbar_arrive_rel_cluster((t & 1) ? rbar1 : rbar0);
        }
    }
}

// ---------------- launcher ---------------------------------------------------
extern "C" void kernel_launch(void* const* d_in, const int* in_sizes, int n_in,
                              void* d_out, int out_size) {
    const float* x  = (const float*)d_in[0];
    const float* h0 = (const float*)d_in[1];
    const float* Wf = (const float*)d_in[2];
    const float* Wi = (const float*)d_in[3];
    const float* Wc = (const float*)d_in[4];
    const float* Wo = (const float*)d_in[5];
    float* out = (float*)d_out;

    k_nop<<<1, 1>>>();
    k_init<<<2048, 256>>>(Wf, Wi, Wc, Wo);
    dim3 gg(NJ / 64, (TN * BN) / 64);   // (16, 2048)
    k_gemm<<<gg, 256>>>(x);
    k_rec<<<128, 256>>>(out, h0);
}